// round 2
// baseline (speedup 1.0000x reference)
#include <cuda_runtime.h>
#include <cstdint>

#define NN   50000
#define EE   800000
#define DINN 128
#define DHH  256
#define DOUTT 64
#define GGG  64
#define TOTE (EE + NN)
#define NCHUNK 49   // ceil(NN/1024)

// ---------------- scratch (static device globals; no runtime allocation) ----
__device__ __align__(16) float g_h[(size_t)NN * DHH];   // GEMM output (per layer)
__device__ __align__(16) float g_f[(size_t)NN * DHH];   // aggregated features (layer output)
__device__ float g_sv[NN];
__device__ float g_dv[NN];
__device__ float g_pool[GGG * DHH];
__device__ int   g_cnt[NN];
__device__ int   g_rowptr[NN + 1];
__device__ int   g_cur[NN];
__device__ int   g_col[TOTE];
__device__ int   g_csum[NCHUNK];
__device__ int   g_i32;      // 1 => index tensors are int32, 0 => int64

// ---------------- dtype-agnostic index load --------------------------------
__device__ __forceinline__ int ld_idx(const void* p, long i) {
    return g_i32 ? ((const int*)p)[i] : (int)((const long long*)p)[i];
}

// Detect index dtype: if data is int64 (values < N), odd 32-bit words are all
// zero high-halves. If int32, odd words are random node ids.
__global__ void k_detect(const int* __restrict__ ei32) {
    __shared__ int any;
    if (threadIdx.x == 0) any = 0;
    __syncthreads();
    if (ei32[2 * threadIdx.x + 1] != 0) atomicOr(&any, 1);
    __syncthreads();
    if (threadIdx.x == 0) g_i32 = any;
}

// ---------------- f32x2 packed-FMA helpers ---------------------------------
__device__ __forceinline__ unsigned long long pk2(float x, float y) {
    unsigned long long r;
    asm("mov.b64 %0, {%1, %2};" : "=l"(r) : "f"(x), "f"(y));
    return r;
}
__device__ __forceinline__ unsigned long long ffma2(unsigned long long a,
                                                    unsigned long long b,
                                                    unsigned long long c) {
    unsigned long long d;
    asm("fma.rn.f32x2 %0, %1, %2, %3;" : "=l"(d) : "l"(a), "l"(b), "l"(c));
    return d;
}
__device__ __forceinline__ void upk2(unsigned long long v, float& lo, float& hi) {
    asm("mov.b64 {%0, %1}, %2;" : "=f"(lo), "=f"(hi) : "l"(v));
}

// ---------------- CSR build -------------------------------------------------
__global__ void k_init_cnt() {
    int i = blockIdx.x * blockDim.x + threadIdx.x;
    if (i < NN) g_cnt[i] = 1;   // self-loop
}

__global__ void k_hist(const void* __restrict__ ei) {
    int e = blockIdx.x * blockDim.x + threadIdx.x;
    if (e < EE) {
        int dst = ld_idx(ei, (long)EE + e);
        atomicAdd(&g_cnt[dst], 1);
    }
}

__global__ void k_chunk_sum() {
    __shared__ int sr[1024];
    int tid = threadIdx.x;
    int i = blockIdx.x * 1024 + tid;
    sr[tid] = (i < NN) ? g_cnt[i] : 0;
    __syncthreads();
    for (int off = 512; off; off >>= 1) {
        if (tid < off) sr[tid] += sr[tid + off];
        __syncthreads();
    }
    if (tid == 0) g_csum[blockIdx.x] = sr[0];
}

__global__ void k_scan_chunks() {
    int run = 0;
    for (int c = 0; c < NCHUNK; c++) {
        int t = g_csum[c];
        g_csum[c] = run;
        run += t;
    }
    g_rowptr[NN] = TOTE;
}

__global__ void k_local_scan() {
    __shared__ int ss[1024];
    int tid = threadIdx.x;
    int i = blockIdx.x * 1024 + tid;
    int v = (i < NN) ? g_cnt[i] : 0;
    ss[tid] = v;
    __syncthreads();
    for (int off = 1; off < 1024; off <<= 1) {
        int add = (tid >= off) ? ss[tid - off] : 0;
        __syncthreads();
        ss[tid] += add;
        __syncthreads();
    }
    if (i < NN) {
        int rp = g_csum[blockIdx.x] + ss[tid] - v;   // exclusive
        g_rowptr[i] = rp;
        g_cur[i] = rp;
    }
}

__global__ void k_scatter(const void* __restrict__ ei) {
    int idx = blockIdx.x * blockDim.x + threadIdx.x;
    if (idx < EE) {
        int src = ld_idx(ei, idx);
        int dst = ld_idx(ei, (long)EE + idx);
        int pos = atomicAdd(&g_cur[dst], 1);
        g_col[pos] = src;
    } else if (idx < TOTE) {
        int i = idx - EE;
        int pos = atomicAdd(&g_cur[i], 1);
        g_col[pos] = i;
    }
}

// ---------------- GEMM: C[M,256] = A[M,K] @ B[K,256]  (f32x2 packed FMA) ----
#define BM 128
#define BN 64
#define BK 16
#define BMP 132   // padded lead dim for As

__global__ __launch_bounds__(256) void k_gemm(const float* __restrict__ A,
                                              const float* __restrict__ B,
                                              float* __restrict__ C,
                                              int M, int K) {
    __shared__ float As[BK][BMP];
    __shared__ float Bs[BK][BN];

    int t = threadIdx.x;
    int m0 = blockIdx.y * BM;
    int n0 = blockIdx.x * BN;
    int tx = t & 15;          // col group (4 cols)
    int ty = t >> 4;          // row group (8 rows)
    int col = n0 + tx * 4;
    int row = m0 + ty * 8;

    unsigned long long acc[4][4];
#pragma unroll
    for (int a = 0; a < 4; a++)
#pragma unroll
        for (int b = 0; b < 4; b++) acc[a][b] = 0ull;

    for (int kt = 0; kt < K; kt += BK) {
        // load A tile (transposed into As)
#pragma unroll
        for (int l = 0; l < 2; l++) {
            int idx = t + l * 256;
            int arow = idx >> 2;
            int ac = (idx & 3) * 4;
            int gr = m0 + arow;
            float4 v = make_float4(0.f, 0.f, 0.f, 0.f);
            if (gr < M) v = *(const float4*)(A + (size_t)gr * K + kt + ac);
            As[ac + 0][arow] = v.x;
            As[ac + 1][arow] = v.y;
            As[ac + 2][arow] = v.z;
            As[ac + 3][arow] = v.w;
        }
        // load B tile
        {
            int brow = t >> 4;
            int bc = (t & 15) * 4;
            float4 v = *(const float4*)(B + (size_t)(kt + brow) * DHH + n0 + bc);
            *(float4*)&Bs[brow][bc] = v;
        }
        __syncthreads();

#pragma unroll
        for (int k = 0; k < BK; k++) {
            float4 a0 = *(const float4*)&As[k][ty * 8];
            float4 a1 = *(const float4*)&As[k][ty * 8 + 4];
            float4 b = *(const float4*)&Bs[k][tx * 4];
            unsigned long long ap0 = pk2(a0.x, a0.y);
            unsigned long long ap1 = pk2(a0.z, a0.w);
            unsigned long long ap2 = pk2(a1.x, a1.y);
            unsigned long long ap3 = pk2(a1.z, a1.w);
            unsigned long long bb0 = pk2(b.x, b.x);
            unsigned long long bb1 = pk2(b.y, b.y);
            unsigned long long bb2 = pk2(b.z, b.z);
            unsigned long long bb3 = pk2(b.w, b.w);
            acc[0][0] = ffma2(ap0, bb0, acc[0][0]);
            acc[0][1] = ffma2(ap0, bb1, acc[0][1]);
            acc[0][2] = ffma2(ap0, bb2, acc[0][2]);
            acc[0][3] = ffma2(ap0, bb3, acc[0][3]);
            acc[1][0] = ffma2(ap1, bb0, acc[1][0]);
            acc[1][1] = ffma2(ap1, bb1, acc[1][1]);
            acc[1][2] = ffma2(ap1, bb2, acc[1][2]);
            acc[1][3] = ffma2(ap1, bb3, acc[1][3]);
            acc[2][0] = ffma2(ap2, bb0, acc[2][0]);
            acc[2][1] = ffma2(ap2, bb1, acc[2][1]);
            acc[2][2] = ffma2(ap2, bb2, acc[2][2]);
            acc[2][3] = ffma2(ap2, bb3, acc[2][3]);
            acc[3][0] = ffma2(ap3, bb0, acc[3][0]);
            acc[3][1] = ffma2(ap3, bb1, acc[3][1]);
            acc[3][2] = ffma2(ap3, bb2, acc[3][2]);
            acc[3][3] = ffma2(ap3, bb3, acc[3][3]);
        }
        __syncthreads();
    }

#pragma unroll
    for (int m2 = 0; m2 < 4; m2++) {
        int r0 = row + m2 * 2;
        int r1 = r0 + 1;
#pragma unroll
        for (int j = 0; j < 4; j++) {
            float lo, hi;
            upk2(acc[m2][j], lo, hi);
            if (r0 < M) C[(size_t)r0 * DHH + col + j] = lo;
            if (r1 < M) C[(size_t)r1 * DHH + col + j] = hi;
        }
    }
}

// ---------------- per-node attention scalars s_i, d_i -----------------------
__global__ void k_sd(const float* __restrict__ asrc, const float* __restrict__ adst) {
    int gid = blockIdx.x * blockDim.x + threadIdx.x;
    int warp = gid >> 5;
    int lane = threadIdx.x & 31;
    if (warp >= NN) return;
    const float4* hp = (const float4*)(g_h + (size_t)warp * DHH);
    const float4* ap = (const float4*)asrc;
    const float4* dp = (const float4*)adst;
    float s = 0.f, d = 0.f;
#pragma unroll
    for (int q = 0; q < 2; q++) {
        float4 v = hp[lane + q * 32];
        float4 a = ap[lane + q * 32];
        float4 b = dp[lane + q * 32];
        s += v.x * a.x + v.y * a.y + v.z * a.z + v.w * a.w;
        d += v.x * b.x + v.y * b.y + v.z * b.z + v.w * b.w;
    }
#pragma unroll
    for (int o = 16; o; o >>= 1) {
        s += __shfl_xor_sync(0xffffffffu, s, o);
        d += __shfl_xor_sync(0xffffffffu, d, o);
    }
    if (lane == 0) { g_sv[warp] = s; g_dv[warp] = d; }
}

// ---------------- per-dst-node softmax + weighted aggregation ---------------
// one 256-thread block per node; thread tid == feature index
__global__ __launch_bounds__(256) void k_aggr(const float* __restrict__ bias) {
    int i = blockIdx.x;
    int tid = threadIdx.x;
    int beg = g_rowptr[i];
    int end = g_rowptr[i + 1];
    float di = g_dv[i];

    // pass A: online softmax stats per thread
    float m = -1e30f, den = 0.f;
    for (int j = beg + tid; j < end; j += 256) {
        float e = g_sv[g_col[j]] + di;
        e = (e > 0.f) ? e : 0.2f * e;
        if (e > m) { den *= __expf(m - e); m = e; }
        den += __expf(e - m);
    }

    __shared__ float sm_m[256], sm_d[256];
    sm_m[tid] = m; sm_d[tid] = den;
    __syncthreads();
    for (int off = 128; off; off >>= 1) {
        if (tid < off) {
            float m2 = sm_m[tid + off], d2 = sm_d[tid + off];
            float M = fmaxf(m, m2);
            den = den * __expf(m - M) + d2 * __expf(m2 - M);
            m = M;
            sm_m[tid] = m; sm_d[tid] = den;
        }
        __syncthreads();
    }
    float Mtot = sm_m[0];
    float inv = 1.0f / sm_d[0];

    // pass B: weighted feature accumulation, 32-edge chunks
    __shared__ float s_alpha[32];
    __shared__ int s_col[32];
    float acc = 0.f;
    for (int base = beg; base < end; base += 32) {
        int cnt = min(32, end - base);
        __syncthreads();
        if (tid < cnt) {
            int c = g_col[base + tid];
            float e = g_sv[c] + di;
            e = (e > 0.f) ? e : 0.2f * e;
            s_alpha[tid] = __expf(e - Mtot) * inv;
            s_col[tid] = c;
        }
        __syncthreads();
        for (int q = 0; q < cnt; q++)
            acc += s_alpha[q] * g_h[(size_t)s_col[q] * DHH + tid];
    }
    g_f[(size_t)i * DHH + tid] = fmaxf(acc + bias[tid], 0.f);   // +b, ReLU
}

// ---------------- pooling ---------------------------------------------------
__global__ void k_zero_pool() {
    int i = blockIdx.x * blockDim.x + threadIdx.x;
    if (i < GGG * DHH) g_pool[i] = 0.f;
}

__global__ void k_pool(const void* __restrict__ batch) {
    __shared__ int sb[64];
    int base = blockIdx.x * 64;
    int tid = threadIdx.x;   // feature
    if (tid < 64) sb[tid] = (base + tid < NN) ? ld_idx(batch, base + tid) : -1;
    __syncthreads();
    float acc = 0.f;
    int cur = -1;
    for (int q = 0; q < 64; q++) {
        int g = sb[q];
        if (g < 0) break;
        if (g != cur) {
            if (cur >= 0) atomicAdd(&g_pool[cur * DHH + tid], acc);
            acc = 0.f; cur = g;
        }
        acc += g_f[(size_t)(base + q) * DHH + tid];
    }
    if (cur >= 0) atomicAdd(&g_pool[cur * DHH + tid], acc);
}

// ---------------- final FC --------------------------------------------------
__global__ void k_fc(const float* __restrict__ fcW, const float* __restrict__ fcb,
                     float* __restrict__ out) {
    int g = blockIdx.x;
    int o = threadIdx.x;   // 64
    float acc = fcb[o];
    for (int f = 0; f < DHH; f++)
        acc += g_pool[g * DHH + f] * fcW[f * DOUTT + o];
    out[g * DOUTT + o] = acc;
}

// ---------------- launch ----------------------------------------------------
extern "C" void kernel_launch(void* const* d_in, const int* in_sizes, int n_in,
                              void* d_out, int out_size) {
    const float* x = (const float*)d_in[0];
    const void* ei = d_in[1];
    const void* batch = d_in[2];
    const float* W[3]    = {(const float*)d_in[3], (const float*)d_in[7],  (const float*)d_in[11]};
    const float* asrc[3] = {(const float*)d_in[4], (const float*)d_in[8],  (const float*)d_in[12]};
    const float* adst[3] = {(const float*)d_in[5], (const float*)d_in[9],  (const float*)d_in[13]};
    const float* bias[3] = {(const float*)d_in[6], (const float*)d_in[10], (const float*)d_in[14]};
    const float* fcW = (const float*)d_in[15];
    const float* fcb = (const float*)d_in[16];
    float* out = (float*)d_out;

    void *hp = nullptr, *fp = nullptr;
    cudaGetSymbolAddress(&hp, g_h);
    cudaGetSymbolAddress(&fp, g_f);
    float* hbuf = (float*)hp;
    float* fbuf = (float*)fp;

    // dtype detection + CSR build
    k_detect<<<1, 256>>>((const int*)ei);
    k_init_cnt<<<(NN + 255) / 256, 256>>>();
    k_hist<<<(EE + 255) / 256, 256>>>(ei);
    k_chunk_sum<<<NCHUNK, 1024>>>();
    k_scan_chunks<<<1, 1>>>();
    k_local_scan<<<NCHUNK, 1024>>>();
    k_scatter<<<(TOTE + 255) / 256, 256>>>(ei);

    dim3 ggrid(DHH / BN, (NN + BM - 1) / BM);
    for (int l = 0; l < 3; l++) {
        const float* A = (l == 0) ? x : fbuf;
        int K = (l == 0) ? DINN : DHH;
        k_gemm<<<ggrid, 256>>>(A, W[l], hbuf, NN, K);
        k_sd<<<(NN + 7) / 8, 256>>>(asrc[l], adst[l]);
        k_aggr<<<NN, 256>>>(bias[l]);
    }

    k_zero_pool<<<(GGG * DHH + 255) / 256, 256>>>();
    k_pool<<<(NN + 63) / 64, 256>>>(batch);
    k_fc<<<GGG, DOUTT>>>(fcW, fcb, out);
}

// round 6
// speedup vs baseline: 1.1725x; 1.1725x over previous
#include <cuda_runtime.h>
#include <cuda_bf16.h>
#include <cstdint>

#define NN   50000
#define EE   800000
#define DINN 128
#define DHH  256
#define DOUTT 64
#define GGG  64
#define TOTE (EE + NN)
#define NCHUNK 49   // ceil(NN/1024)

// ---------------- scratch (static device globals) ---------------------------
__device__ __align__(16) float g_h[(size_t)NN * DHH];   // GEMM output (per layer)
__device__ __align__(16) float g_f[(size_t)NN * DHH];   // aggregated features
__device__ __align__(16) __nv_bfloat16 g_ah[(size_t)NN * DHH];
__device__ __align__(16) __nv_bfloat16 g_al[(size_t)NN * DHH];
__device__ __align__(16) __nv_bfloat16 g_bh[DHH * DHH];   // Wt hi [256][K]
__device__ __align__(16) __nv_bfloat16 g_bl[DHH * DHH];   // Wt lo [256][K]
__device__ float g_sv[NN];
__device__ float g_dv[NN];
__device__ float g_pool[GGG * DHH];
__device__ int   g_cnt[NN];
__device__ int   g_rowptr[NN + 1];
__device__ int   g_cur[NN];
__device__ int   g_col[TOTE];
__device__ int   g_csum[NCHUNK];
__device__ int   g_i32;      // 1 => index tensors are int32, 0 => int64

// ---------------- dtype-agnostic index load ---------------------------------
__device__ __forceinline__ int ld_idx(const void* p, long i) {
    return g_i32 ? ((const int*)p)[i] : (int)((const long long*)p)[i];
}

__global__ void k_detect(const int* __restrict__ ei32) {
    __shared__ int any;
    if (threadIdx.x == 0) any = 0;
    __syncthreads();
    if (ei32[2 * threadIdx.x + 1] != 0) atomicOr(&any, 1);
    __syncthreads();
    if (threadIdx.x == 0) g_i32 = any;
}

// ---------------- CSR build -------------------------------------------------
__global__ void k_init_cnt() {
    int i = blockIdx.x * blockDim.x + threadIdx.x;
    if (i < NN) g_cnt[i] = 1;   // self-loop
}

__global__ void k_hist(const void* __restrict__ ei) {
    int e = blockIdx.x * blockDim.x + threadIdx.x;
    if (e < EE) atomicAdd(&g_cnt[ld_idx(ei, (long)EE + e)], 1);
}

__global__ void k_chunk_sum() {
    __shared__ int sr[1024];
    int tid = threadIdx.x;
    int i = blockIdx.x * 1024 + tid;
    sr[tid] = (i < NN) ? g_cnt[i] : 0;
    __syncthreads();
    for (int off = 512; off; off >>= 1) {
        if (tid < off) sr[tid] += sr[tid + off];
        __syncthreads();
    }
    if (tid == 0) g_csum[blockIdx.x] = sr[0];
}

__global__ void k_scan_chunks() {
    int run = 0;
    for (int c = 0; c < NCHUNK; c++) {
        int t = g_csum[c];
        g_csum[c] = run;
        run += t;
    }
    g_rowptr[NN] = TOTE;
}

__global__ void k_local_scan() {
    __shared__ int ss[1024];
    int tid = threadIdx.x;
    int i = blockIdx.x * 1024 + tid;
    int v = (i < NN) ? g_cnt[i] : 0;
    ss[tid] = v;
    __syncthreads();
    for (int off = 1; off < 1024; off <<= 1) {
        int add = (tid >= off) ? ss[tid - off] : 0;
        __syncthreads();
        ss[tid] += add;
        __syncthreads();
    }
    if (i < NN) {
        int rp = g_csum[blockIdx.x] + ss[tid] - v;   // exclusive
        g_rowptr[i] = rp;
        g_cur[i] = rp;
    }
}

__global__ void k_scatter(const void* __restrict__ ei) {
    int idx = blockIdx.x * blockDim.x + threadIdx.x;
    if (idx < EE) {
        int src = ld_idx(ei, idx);
        int dst = ld_idx(ei, (long)EE + idx);
        int pos = atomicAdd(&g_cur[dst], 1);
        g_col[pos] = src;
    } else if (idx < TOTE) {
        int i = idx - EE;
        int pos = atomicAdd(&g_cur[i], 1);
        g_col[pos] = i;
    }
}

// ---------------- fp32 -> bf16 hi/lo conversion -----------------------------
__global__ void k_cvt_a(const float4* __restrict__ A, int n4) {
    int i = blockIdx.x * blockDim.x + threadIdx.x;
    if (i >= n4) return;
    float4 v = A[i];
    __nv_bfloat16 hx = __float2bfloat16_rn(v.x);
    __nv_bfloat16 hy = __float2bfloat16_rn(v.y);
    __nv_bfloat16 hz = __float2bfloat16_rn(v.z);
    __nv_bfloat16 hw = __float2bfloat16_rn(v.w);
    __nv_bfloat162* oh = (__nv_bfloat162*)g_ah;
    __nv_bfloat162* ol = (__nv_bfloat162*)g_al;
    oh[2 * i]     = __nv_bfloat162(hx, hy);
    oh[2 * i + 1] = __nv_bfloat162(hz, hw);
    ol[2 * i]     = __nv_bfloat162(__float2bfloat16_rn(v.x - __bfloat162float(hx)),
                                   __float2bfloat16_rn(v.y - __bfloat162float(hy)));
    ol[2 * i + 1] = __nv_bfloat162(__float2bfloat16_rn(v.z - __bfloat162float(hz)),
                                   __float2bfloat16_rn(v.w - __bfloat162float(hw)));
}

// W [K, 256] fp32 -> Wt_hi/Wt_lo [256, K] bf16 (transposed, K contiguous)
__global__ void k_cvt_w(const float* __restrict__ W, int K) {
    int i = blockIdx.x * blockDim.x + threadIdx.x;
    if (i >= K * DHH) return;
    int n = i / K, k = i - n * K;
    float f = W[(size_t)k * DHH + n];
    __nv_bfloat16 h = __float2bfloat16_rn(f);
    g_bh[i] = h;
    g_bl[i] = __float2bfloat16_rn(f - __bfloat162float(h));
}

// ---------------- HMMA bf16 GEMM: C[M,256] = A[M,K] @ Wt^T ------------------
// mma.sync m16n8k16 bf16, hi/lo 3-pass split. Fragments via explicit LDS at
// documented PTX fragment coordinates. B resides in smem for FULL K (loaded
// once); B fragment addressing therefore includes the global kt offset.
__device__ __forceinline__ void mma16816(float* c, const uint32_t* a, uint32_t b0, uint32_t b1) {
    asm volatile("mma.sync.aligned.m16n8k16.row.col.f32.bf16.bf16.f32 "
                 "{%0,%1,%2,%3}, {%4,%5,%6,%7}, {%8,%9}, {%0,%1,%2,%3};"
                 : "+f"(c[0]), "+f"(c[1]), "+f"(c[2]), "+f"(c[3])
                 : "r"(a[0]), "r"(a[1]), "r"(a[2]), "r"(a[3]), "r"(b0), "r"(b1));
}

#define ASTR 80   // A row stride bytes (32 bf16 + 8 pad)

__global__ __launch_bounds__(256) void k_gemm_mma(
    const __nv_bfloat16* __restrict__ Ah, const __nv_bfloat16* __restrict__ Al,
    const __nv_bfloat16* __restrict__ Bh, const __nv_bfloat16* __restrict__ Bl,
    float* __restrict__ C, int M, int K)
{
    extern __shared__ char smem[];
    const int BSTR = 2 * K + 16;            // B row stride bytes (odd multiple of 16)
    char* sAh = smem;                       // 128 * 80 = 10240
    char* sAl = smem + 10240;               // 10240
    char* sBh = smem + 20480;               // 64 * BSTR
    char* sBl = sBh + 64 * BSTR;

    int tid = threadIdx.x;
    int wid = tid >> 5, lane = tid & 31;
    int warp_m = wid >> 1, warp_n = wid & 1;
    int group = lane >> 2, tq = lane & 3;
    int m0 = blockIdx.y * 128;
    int n0 = blockIdx.x * 64;

    // ---- load B slice (64 rows x K, hi+lo) once ----
    {
        int kc8 = K >> 3;                   // 16-byte chunks per row
        for (int idx = tid; idx < 64 * kc8; idx += 256) {
            int n = idx / kc8, c = idx - n * kc8;
            size_t src = (size_t)(n0 + n) * K + c * 8;
            *(uint4*)(sBh + n * BSTR + c * 16) = *(const uint4*)(Bh + src);
            *(uint4*)(sBl + n * BSTR + c * 16) = *(const uint4*)(Bl + src);
        }
    }

    float acc[2][4][4];
#pragma unroll
    for (int mt = 0; mt < 2; mt++)
#pragma unroll
        for (int nt = 0; nt < 4; nt++)
#pragma unroll
            for (int q = 0; q < 4; q++) acc[mt][nt][q] = 0.f;

    for (int kt = 0; kt < K; kt += 32) {
        __syncthreads();
        // ---- stage A tile (128 x 32, hi+lo) ----
#pragma unroll
        for (int l = 0; l < 2; l++) {
            int idx = tid + l * 256;        // 512 x 16B chunks
            int r = idx >> 2, c = idx & 3;
            uint4 vh = make_uint4(0, 0, 0, 0), vl = make_uint4(0, 0, 0, 0);
            if (m0 + r < M) {
                size_t src = (size_t)(m0 + r) * K + kt + c * 8;
                vh = *(const uint4*)(Ah + src);
                vl = *(const uint4*)(Al + src);
            }
            *(uint4*)(sAh + r * ASTR + c * 16) = vh;
            *(uint4*)(sAl + r * ASTR + c * 16) = vl;
        }
        __syncthreads();

#pragma unroll
        for (int kk = 0; kk < 32; kk += 16) {
            int kbA = (kk + 2 * tq) * 2;          // A tile-local k byte offset
            int kbB = (kt + kk + 2 * tq) * 2;     // B GLOBAL k byte offset (the R4/R5 fix)
            uint32_t ah[2][4], al[2][4];
#pragma unroll
            for (int mt = 0; mt < 2; mt++) {
                int rb = warp_m * 32 + mt * 16 + group;
                uint32_t o0 = (uint32_t)rb * ASTR + kbA;
                uint32_t o1 = (uint32_t)(rb + 8) * ASTR + kbA;
                ah[mt][0] = *(const uint32_t*)(sAh + o0);
                ah[mt][1] = *(const uint32_t*)(sAh + o1);
                ah[mt][2] = *(const uint32_t*)(sAh + o0 + 16);
                ah[mt][3] = *(const uint32_t*)(sAh + o1 + 16);
                al[mt][0] = *(const uint32_t*)(sAl + o0);
                al[mt][1] = *(const uint32_t*)(sAl + o1);
                al[mt][2] = *(const uint32_t*)(sAl + o0 + 16);
                al[mt][3] = *(const uint32_t*)(sAl + o1 + 16);
            }
            uint32_t bh0[4], bh1[4], bl0[4], bl1[4];
#pragma unroll
            for (int nt = 0; nt < 4; nt++) {
                int n = warp_n * 32 + nt * 8 + group;
                uint32_t o = (uint32_t)n * BSTR + kbB;
                bh0[nt] = *(const uint32_t*)(sBh + o);
                bh1[nt] = *(const uint32_t*)(sBh + o + 16);
                bl0[nt] = *(const uint32_t*)(sBl + o);
                bl1[nt] = *(const uint32_t*)(sBl + o + 16);
            }
#pragma unroll
            for (int mt = 0; mt < 2; mt++)
#pragma unroll
                for (int nt = 0; nt < 4; nt++) {
                    mma16816(acc[mt][nt], ah[mt], bh0[nt], bh1[nt]);   // hi*hi
                    mma16816(acc[mt][nt], al[mt], bh0[nt], bh1[nt]);   // lo*hi
                    mma16816(acc[mt][nt], ah[mt], bl0[nt], bl1[nt]);   // hi*lo
                }
        }
    }

    // ---- epilogue (C fragment: c0,c1 row=group, c2,c3 row=group+8) ----
#pragma unroll
    for (int mt = 0; mt < 2; mt++) {
        int r0 = m0 + warp_m * 32 + mt * 16 + group;
#pragma unroll
        for (int nt = 0; nt < 4; nt++) {
            int col = n0 + warp_n * 32 + nt * 8 + tq * 2;
            if (r0 < M)
                *(float2*)(C + (size_t)r0 * DHH + col) = make_float2(acc[mt][nt][0], acc[mt][nt][1]);
            if (r0 + 8 < M)
                *(float2*)(C + (size_t)(r0 + 8) * DHH + col) = make_float2(acc[mt][nt][2], acc[mt][nt][3]);
        }
    }
}

// ---------------- per-node attention scalars s_i, d_i -----------------------
__global__ void k_sd(const float* __restrict__ asrc, const float* __restrict__ adst) {
    int gid = blockIdx.x * blockDim.x + threadIdx.x;
    int warp = gid >> 5;
    int lane = threadIdx.x & 31;
    if (warp >= NN) return;
    const float4* hp = (const float4*)(g_h + (size_t)warp * DHH);
    const float4* ap = (const float4*)asrc;
    const float4* dp = (const float4*)adst;
    float s = 0.f, d = 0.f;
#pragma unroll
    for (int q = 0; q < 2; q++) {
        float4 v = hp[lane + q * 32];
        float4 a = ap[lane + q * 32];
        float4 b = dp[lane + q * 32];
        s += v.x * a.x + v.y * a.y + v.z * a.z + v.w * a.w;
        d += v.x * b.x + v.y * b.y + v.z * b.z + v.w * b.w;
    }
#pragma unroll
    for (int o = 16; o; o >>= 1) {
        s += __shfl_xor_sync(0xffffffffu, s, o);
        d += __shfl_xor_sync(0xffffffffu, d, o);
    }
    if (lane == 0) { g_sv[warp] = s; g_dv[warp] = d; }
}

// ---------------- per-dst-node softmax + weighted aggregation ---------------
__global__ __launch_bounds__(256) void k_aggr(const float* __restrict__ bias) {
    int i = blockIdx.x;
    int tid = threadIdx.x;
    int beg = g_rowptr[i];
    int end = g_rowptr[i + 1];
    float di = g_dv[i];

    float m = -1e30f, den = 0.f;
    for (int j = beg + tid; j < end; j += 256) {
        float e = g_sv[g_col[j]] + di;
        e = (e > 0.f) ? e : 0.2f * e;
        if (e > m) { den *= __expf(m - e); m = e; }
        den += __expf(e - m);
    }

    __shared__ float sm_m[256], sm_d[256];
    sm_m[tid] = m; sm_d[tid] = den;
    __syncthreads();
    for (int off = 128; off; off >>= 1) {
        if (tid < off) {
            float m2 = sm_m[tid + off], d2 = sm_d[tid + off];
            float M = fmaxf(m, m2);
            den = den * __expf(m - M) + d2 * __expf(m2 - M);
            m = M;
            sm_m[tid] = m; sm_d[tid] = den;
        }
        __syncthreads();
    }
    float Mtot = sm_m[0];
    float inv = 1.0f / sm_d[0];

    __shared__ float s_alpha[32];
    __shared__ int s_col[32];
    float acc = 0.f;
    for (int base = beg; base < end; base += 32) {
        int cnt = min(32, end - base);
        __syncthreads();
        if (tid < cnt) {
            int c = g_col[base + tid];
            float e = g_sv[c] + di;
            e = (e > 0.f) ? e : 0.2f * e;
            s_alpha[tid] = __expf(e - Mtot) * inv;
            s_col[tid] = c;
        }
        __syncthreads();
        for (int q = 0; q < cnt; q++)
            acc += s_alpha[q] * g_h[(size_t)s_col[q] * DHH + tid];
    }
    g_f[(size_t)i * DHH + tid] = fmaxf(acc + bias[tid], 0.f);
}

// ---------------- pooling ---------------------------------------------------
__global__ void k_zero_pool() {
    int i = blockIdx.x * blockDim.x + threadIdx.x;
    if (i < GGG * DHH) g_pool[i] = 0.f;
}

__global__ void k_pool(const void* __restrict__ batch) {
    __shared__ int sb[64];
    int base = blockIdx.x * 64;
    int tid = threadIdx.x;
    if (tid < 64) sb[tid] = (base + tid < NN) ? ld_idx(batch, base + tid) : -1;
    __syncthreads();
    float acc = 0.f;
    int cur = -1;
    for (int q = 0; q < 64; q++) {
        int g = sb[q];
        if (g < 0) break;
        if (g != cur) {
            if (cur >= 0) atomicAdd(&g_pool[cur * DHH + tid], acc);
            acc = 0.f; cur = g;
        }
        acc += g_f[(size_t)(base + q) * DHH + tid];
    }
    if (cur >= 0) atomicAdd(&g_pool[cur * DHH + tid], acc);
}

// ---------------- final FC --------------------------------------------------
__global__ void k_fc(const float* __restrict__ fcW, const float* __restrict__ fcb,
                     float* __restrict__ out) {
    int g = blockIdx.x;
    int o = threadIdx.x;
    float acc = fcb[o];
    for (int f = 0; f < DHH; f++)
        acc += g_pool[g * DHH + f] * fcW[f * DOUTT + o];
    out[g * DOUTT + o] = acc;
}

// ---------------- launch ----------------------------------------------------
extern "C" void kernel_launch(void* const* d_in, const int* in_sizes, int n_in,
                              void* d_out, int out_size) {
    const float* x = (const float*)d_in[0];
    const void* ei = d_in[1];
    const void* batch = d_in[2];
    const float* W[3]    = {(const float*)d_in[3], (const float*)d_in[7],  (const float*)d_in[11]};
    const float* asrc[3] = {(const float*)d_in[4], (const float*)d_in[8],  (const float*)d_in[12]};
    const float* adst[3] = {(const float*)d_in[5], (const float*)d_in[9],  (const float*)d_in[13]};
    const float* bias[3] = {(const float*)d_in[6], (const float*)d_in[10], (const float*)d_in[14]};
    const float* fcW = (const float*)d_in[15];
    const float* fcb = (const float*)d_in[16];
    float* out = (float*)d_out;

    void *hp = nullptr, *fp = nullptr, *ahp = nullptr, *alp = nullptr, *bhp = nullptr, *blp = nullptr;
    cudaGetSymbolAddress(&hp, g_h);
    cudaGetSymbolAddress(&fp, g_f);
    cudaGetSymbolAddress(&ahp, g_ah);
    cudaGetSymbolAddress(&alp, g_al);
    cudaGetSymbolAddress(&bhp, g_bh);
    cudaGetSymbolAddress(&blp, g_bl);
    float* hbuf = (float*)hp;
    float* fbuf = (float*)fp;

    const int SMEM_MMA = 20480 + 2 * 64 * (2 * DHH + 16);   // 88064 bytes (K=256)
    cudaFuncSetAttribute(k_gemm_mma, cudaFuncAttributeMaxDynamicSharedMemorySize, SMEM_MMA);

    // dtype detection + CSR build
    k_detect<<<1, 256>>>((const int*)ei);
    k_init_cnt<<<(NN + 255) / 256, 256>>>();
    k_hist<<<(EE + 255) / 256, 256>>>(ei);
    k_chunk_sum<<<NCHUNK, 1024>>>();
    k_scan_chunks<<<1, 1>>>();
    k_local_scan<<<NCHUNK, 1024>>>();
    k_scatter<<<(TOTE + 255) / 256, 256>>>(ei);

    for (int l = 0; l < 3; l++) {
        const float* A = (l == 0) ? x : fbuf;
        int K = (l == 0) ? DINN : DHH;
        int n4 = NN * K / 4;
        int smem = 20480 + 2 * 64 * (2 * K + 16);
        k_cvt_a<<<(n4 + 255) / 256, 256>>>((const float4*)A, n4);
        k_cvt_w<<<(K * DHH + 255) / 256, 256>>>(W[l], K);
        dim3 grid(DHH / 64, (NN + 127) / 128);
        k_gemm_mma<<<grid, 256, smem>>>(
            (const __nv_bfloat16*)ahp, (const __nv_bfloat16*)alp,
            (const __nv_bfloat16*)bhp, (const __nv_bfloat16*)blp,
            hbuf, NN, K);
        k_sd<<<(NN + 7) / 8, 256>>>(asrc[l], adst[l]);
        k_aggr<<<NN, 256>>>(bias[l]);
    }

    k_zero_pool<<<(GGG * DHH + 255) / 256, 256>>>();
    k_pool<<<(NN + 63) / 64, 256>>>(batch);
    k_fc<<<GGG, DOUTT>>>(fcW, fcb, out);
}